// round 4
// baseline (speedup 1.0000x reference)
#include <cuda_runtime.h>
#include <cuda_bf16.h>
#include <cstdint>

#define BATCH 8
#define CDIM  512
#define NDIM  4096
#define MDIM  64
#define EPSV  1e-6f
#define PITCH 72   // bf16 elems per smem row; 36 words -> stride 4 mod 32 banks: conflict-free frags

// ---- scratch (device globals; allocation is forbidden) ----
__device__ float         g_gmax[BATCH*CDIM];
__device__ float         g_gsum[BATCH*CDIM];
__device__ float         g_ksum[BATCH*MDIM];
__device__ float         g_KX[BATCH*MDIM*CDIM];
__device__ float         g_norm[BATCH*NDIM];
__device__ __nv_bfloat16 g_wvb[CDIM*CDIM];
__device__ __nv_bfloat16 g_Kf[BATCH*MDIM*NDIM];    // [b][m][n]
__device__ __nv_bfloat16 g_Qft[BATCH*NDIM*MDIM];   // [b][n][m]
__device__ __nv_bfloat16 g_KVt[BATCH*CDIM*MDIM];   // [b][c][m]

__device__ __forceinline__ uint32_t pack2(float a, float b){
    __nv_bfloat162 h = __floats2bfloat162_rn(a, b);
    return *reinterpret_cast<uint32_t*>(&h);
}
__device__ __forceinline__ float softplusf(float v){
    return v > 15.f ? v : log1pf(expf(v));
}
__device__ __forceinline__ void atomicMaxF(float* a, float v){
    if (v >= 0.f) atomicMax((int*)a, __float_as_int(v));
    else          atomicMin((unsigned int*)a, __float_as_uint(v));
}
__device__ __forceinline__ void mma16816(float c[4], uint32_t a0, uint32_t a1, uint32_t a2, uint32_t a3,
                                         uint32_t b0, uint32_t b1){
    asm volatile("mma.sync.aligned.m16n8k16.row.col.f32.bf16.bf16.f32 "
                 "{%0,%1,%2,%3},{%4,%5,%6,%7},{%8,%9},{%0,%1,%2,%3};"
                 : "+f"(c[0]), "+f"(c[1]), "+f"(c[2]), "+f"(c[3])
                 : "r"(a0), "r"(a1), "r"(a2), "r"(a3), "r"(b0), "r"(b1));
}

// ---- K0: zero accumulators + convert wv -> bf16 (every replay) ----
__global__ __launch_bounds__(256) void k_prep(const float* __restrict__ wv){
    int i = blockIdx.x*256 + threadIdx.x;
    if (i < BATCH*MDIM*CDIM) g_KX[i] = 0.f;
    if (i < CDIM*CDIM)       g_wvb[i] = __float2bfloat16(wv[i]);
    if (i < BATCH*MDIM)      g_ksum[i] = 0.f;
    if (i < BATCH*CDIM){ g_gmax[i] = -1e30f; g_gsum[i] = 0.f; }
}

// ---- K2: fused Q/K. One x pass: Kf[b][m][n] (+ksum), Qft[b][n][m] ----
__global__ __launch_bounds__(256) void k_qk(const float* __restrict__ x,
                                            const float* __restrict__ wq, const float* __restrict__ bq,
                                            const float* __restrict__ wk, const float* __restrict__ bk){
    __shared__ __nv_bfloat16 sWk[64*PITCH], sWq[64*PITCH], sX[128*PITCH];
    __shared__ float sSum[64];
    const int t = threadIdx.x, b = blockIdx.y, n0 = blockIdx.x*128;
    const int lane = t & 31, w = t >> 5, gr = lane >> 2, tg = lane & 3;
    const int wm = (w >> 2)*32, wn = (w & 3)*32;    // K output: rows m, cols n
    const int wr = (w & 3)*32, wc2 = (w >> 2)*32;   // Q output: rows n, cols m
    const float* xb = x + (size_t)b*CDIM*NDIM;
    float ak[2][4][4], aq[2][4][4];
    #pragma unroll
    for (int i=0;i<2;i++) for (int j=0;j<4;j++) for (int q=0;q<4;q++){ ak[i][j][q]=0.f; aq[i][j][q]=0.f; }
    if (t < 64) sSum[t] = 0.f;

    for (int k0 = 0; k0 < CDIM; k0 += 64){
        #pragma unroll
        for (int ii = 0; ii < 8; ii++){
            int i = t + ii*256, m = i >> 5, kp = i & 31;
            float2 v = *(const float2*)&wk[m*CDIM + k0 + 2*kp];
            *(uint32_t*)&sWk[m*PITCH + 2*kp] = pack2(v.x, v.y);
            float2 u = *(const float2*)&wq[m*CDIM + k0 + 2*kp];
            *(uint32_t*)&sWq[m*PITCH + 2*kp] = pack2(u.x, u.y);
        }
        #pragma unroll
        for (int ii = 0; ii < 16; ii++){
            int i = t + ii*256, kp = i >> 7, nn = i & 127;
            float v0 = xb[(size_t)(k0 + 2*kp    )*NDIM + n0 + nn];
            float v1 = xb[(size_t)(k0 + 2*kp + 1)*NDIM + n0 + nn];
            *(uint32_t*)&sX[nn*PITCH + 2*kp] = pack2(v0, v1);
        }
        __syncthreads();
        #pragma unroll
        for (int ks = 0; ks < 4; ks++){
            int kb = ks*16;
            {   // K = wk @ x
                uint32_t a[2][4], bb[4][2];
                #pragma unroll
                for (int mi = 0; mi < 2; mi++){
                    int r = wm + mi*16 + gr;
                    a[mi][0] = *(uint32_t*)&sWk[ r   *PITCH + kb + 2*tg];
                    a[mi][1] = *(uint32_t*)&sWk[(r+8)*PITCH + kb + 2*tg];
                    a[mi][2] = *(uint32_t*)&sWk[ r   *PITCH + kb + 2*tg + 8];
                    a[mi][3] = *(uint32_t*)&sWk[(r+8)*PITCH + kb + 2*tg + 8];
                }
                #pragma unroll
                for (int ni = 0; ni < 4; ni++){
                    int rn = wn + ni*8 + gr;
                    bb[ni][0] = *(uint32_t*)&sX[rn*PITCH + kb + 2*tg];
                    bb[ni][1] = *(uint32_t*)&sX[rn*PITCH + kb + 2*tg + 8];
                }
                #pragma unroll
                for (int mi = 0; mi < 2; mi++)
                    #pragma unroll
                    for (int ni = 0; ni < 4; ni++)
                        mma16816(ak[mi][ni], a[mi][0], a[mi][1], a[mi][2], a[mi][3], bb[ni][0], bb[ni][1]);
            }
            {   // Q^T = x^T @ wq^T
                uint32_t a[2][4], bb[4][2];
                #pragma unroll
                for (int mi = 0; mi < 2; mi++){
                    int r = wr + mi*16 + gr;
                    a[mi][0] = *(uint32_t*)&sX[ r   *PITCH + kb + 2*tg];
                    a[mi][1] = *(uint32_t*)&sX[(r+8)*PITCH + kb + 2*tg];
                    a[mi][2] = *(uint32_t*)&sX[ r   *PITCH + kb + 2*tg + 8];
                    a[mi][3] = *(uint32_t*)&sX[(r+8)*PITCH + kb + 2*tg + 8];
                }
                #pragma unroll
                for (int ni = 0; ni < 4; ni++){
                    int rn = wc2 + ni*8 + gr;
                    bb[ni][0] = *(uint32_t*)&sWq[rn*PITCH + kb + 2*tg];
                    bb[ni][1] = *(uint32_t*)&sWq[rn*PITCH + kb + 2*tg + 8];
                }
                #pragma unroll
                for (int mi = 0; mi < 2; mi++)
                    #pragma unroll
                    for (int ni = 0; ni < 4; ni++)
                        mma16816(aq[mi][ni], a[mi][0], a[mi][1], a[mi][2], a[mi][3], bb[ni][0], bb[ni][1]);
            }
        }
        __syncthreads();
    }
    // K epilogue: softplus, store Kf, row-sum partials
    #pragma unroll
    for (int mi = 0; mi < 2; mi++){
        int r0 = wm + mi*16 + gr;
        float bk0 = bk[r0], bk1 = bk[r0 + 8];
        float rs0 = 0.f, rs1 = 0.f;
        #pragma unroll
        for (int ni = 0; ni < 4; ni++){
            float v00 = softplusf(ak[mi][ni][0] + bk0);
            float v01 = softplusf(ak[mi][ni][1] + bk0);
            float v10 = softplusf(ak[mi][ni][2] + bk1);
            float v11 = softplusf(ak[mi][ni][3] + bk1);
            rs0 += v00 + v01; rs1 += v10 + v11;
            int col = n0 + wn + ni*8 + 2*tg;
            *(uint32_t*)&g_Kf[((size_t)(b*MDIM + r0    ))*NDIM + col] = pack2(v00, v01);
            *(uint32_t*)&g_Kf[((size_t)(b*MDIM + r0 + 8))*NDIM + col] = pack2(v10, v11);
        }
        atomicAdd(&sSum[r0], rs0);
        atomicAdd(&sSum[r0 + 8], rs1);
    }
    // Q epilogue: softplus, store transposed
    #pragma unroll
    for (int mi = 0; mi < 2; mi++){
        int r0 = wr + mi*16 + gr;
        #pragma unroll
        for (int ni = 0; ni < 4; ni++){
            int col = wc2 + ni*8 + 2*tg;
            float bq0 = bq[col], bq1 = bq[col + 1];
            float v00 = softplusf(aq[mi][ni][0] + bq0);
            float v01 = softplusf(aq[mi][ni][1] + bq1);
            float v10 = softplusf(aq[mi][ni][2] + bq0);
            float v11 = softplusf(aq[mi][ni][3] + bq1);
            *(uint32_t*)&g_Qft[((size_t)(b*NDIM + n0 + r0    ))*MDIM + col] = pack2(v00, v01);
            *(uint32_t*)&g_Qft[((size_t)(b*NDIM + n0 + r0 + 8))*MDIM + col] = pack2(v10, v11);
        }
    }
    __syncthreads();
    if (t < 64) atomicAdd(&g_ksum[b*MDIM + t], sSum[t]);
}

// ---- K3: KX[b][m][c] += sum_n Kf[m][n]*x[c][n]  (16-way n-split, atomics)
//      + fused gate partials: rowmax/rowsum of x per (b,c)  ----
__global__ __launch_bounds__(256) void k_kx(const float* __restrict__ x){
    __shared__ __nv_bfloat16 sA[64*PITCH];    // Kf [m][k=n]
    __shared__ __nv_bfloat16 sB[128*PITCH];   // x  [c][k=n]
    __shared__ float sGmx[128], sGsm[128];
    const int t = threadIdx.x, b = blockIdx.z;
    const int c0 = blockIdx.x*128, ns0 = blockIdx.y*256;
    const int lane = t & 31, w = t >> 5, gr = lane >> 2, tg = lane & 3;
    const int wm = (w >> 2)*32, wc = (w & 3)*32;
    const float* xb = x + (size_t)b*CDIM*NDIM;
    float acc[2][4][4];
    #pragma unroll
    for (int i=0;i<2;i++) for (int j=0;j<4;j++) for (int q=0;q<4;q++) acc[i][j][q]=0.f;
    if (t < 128){ sGmx[t] = -1e30f; sGsm[t] = 0.f; }
    __syncthreads();

    for (int kc = 0; kc < 256; kc += 64){
        int nk0 = ns0 + kc;
        #pragma unroll
        for (int ii = 0; ii < 2; ii++){
            int i = t + ii*256, m = i >> 3, q = i & 7;
            *(uint4*)&sA[m*PITCH + q*8] = *(const uint4*)&g_Kf[((size_t)(b*MDIM + m))*NDIM + nk0 + q*8];
        }
        #pragma unroll
        for (int ii = 0; ii < 16; ii++){
            // row cc = 8*ii + w is owned exclusively by warp w -> race-free smem gate accum
            int cc = 8*ii + w, np = lane;
            float2 v = *(const float2*)&xb[(size_t)(c0 + cc)*NDIM + nk0 + 2*np];
            *(uint32_t*)&sB[cc*PITCH + 2*np] = pack2(v.x, v.y);
            float mx = fmaxf(v.x, v.y), sm = v.x + v.y;
            #pragma unroll
            for (int o = 16; o > 0; o >>= 1){
                mx = fmaxf(mx, __shfl_xor_sync(~0u, mx, o));
                sm += __shfl_xor_sync(~0u, sm, o);
            }
            if (lane == 0){ sGmx[cc] = fmaxf(sGmx[cc], mx); sGsm[cc] += sm; }
        }
        __syncthreads();
        #pragma unroll
        for (int ks = 0; ks < 4; ks++){
            int kb = ks*16;
            uint32_t a[2][4], bb[4][2];
            #pragma unroll
            for (int mi = 0; mi < 2; mi++){
                int r = wm + mi*16 + gr;
                a[mi][0] = *(uint32_t*)&sA[ r   *PITCH + kb + 2*tg];
                a[mi][1] = *(uint32_t*)&sA[(r+8)*PITCH + kb + 2*tg];
                a[mi][2] = *(uint32_t*)&sA[ r   *PITCH + kb + 2*tg + 8];
                a[mi][3] = *(uint32_t*)&sA[(r+8)*PITCH + kb + 2*tg + 8];
            }
            #pragma unroll
            for (int ni = 0; ni < 4; ni++){
                int rn = wc + ni*8 + gr;
                bb[ni][0] = *(uint32_t*)&sB[rn*PITCH + kb + 2*tg];
                bb[ni][1] = *(uint32_t*)&sB[rn*PITCH + kb + 2*tg + 8];
            }
            #pragma unroll
            for (int mi = 0; mi < 2; mi++)
                #pragma unroll
                for (int ni = 0; ni < 4; ni++)
                    mma16816(acc[mi][ni], a[mi][0], a[mi][1], a[mi][2], a[mi][3], bb[ni][0], bb[ni][1]);
        }
        __syncthreads();
    }
    #pragma unroll
    for (int mi = 0; mi < 2; mi++){
        int r = wm + mi*16 + gr;
        #pragma unroll
        for (int ni = 0; ni < 4; ni++){
            int col = c0 + wc + ni*8 + 2*tg;
            atomicAdd(&g_KX[(b*MDIM + r    )*CDIM + col    ], acc[mi][ni][0]);
            atomicAdd(&g_KX[(b*MDIM + r    )*CDIM + col + 1], acc[mi][ni][1]);
            atomicAdd(&g_KX[(b*MDIM + r + 8)*CDIM + col    ], acc[mi][ni][2]);
            atomicAdd(&g_KX[(b*MDIM + r + 8)*CDIM + col + 1], acc[mi][ni][3]);
        }
    }
    if (t < 128){
        atomicAdd(&g_gsum[b*CDIM + c0 + t], sGsm[t]);
        atomicMaxF(&g_gmax[b*CDIM + c0 + t], sGmx[t]);
    }
}

// ---- K4: norm[b][n] = 1 / sum_m Qft[n][m]*(ksum[m]+EPS) ----
__global__ __launch_bounds__(256) void k_norm(){
    __shared__ float sk[64];
    int b = blockIdx.y, n = blockIdx.x*256 + threadIdx.x;
    if (threadIdx.x < 64) sk[threadIdx.x] = g_ksum[b*MDIM + threadIdx.x] + EPSV;
    __syncthreads();
    const __nv_bfloat162* row = (const __nv_bfloat162*)&g_Qft[((size_t)(b*NDIM + n))*MDIM];
    float d = 0.f;
    #pragma unroll
    for (int j = 0; j < 32; j++){
        float2 v = __bfloat1622float2(row[j]);
        d += v.x*sk[2*j] + v.y*sk[2*j + 1];
    }
    g_norm[b*NDIM + n] = 1.f/d;
}

// ---- K5: KVt[b][c][m] = gate[c]*(sum_c' wv[c][c']*KX[m][c'] + bv[c]*ksum[m]) ----
__global__ __launch_bounds__(256) void k_kv(const float* __restrict__ bv){
    __shared__ __nv_bfloat16 sA[128*PITCH];   // wv  [c][k]
    __shared__ __nv_bfloat16 sB[64*PITCH];    // KX  [m][k]
    const int t = threadIdx.x, b = blockIdx.y, c0 = blockIdx.x*128;
    const int lane = t & 31, w = t >> 5, gr = lane >> 2, tg = lane & 3;
    const int wc = (w & 3)*32, wm2 = (w >> 2)*32;
    float acc[2][4][4];
    #pragma unroll
    for (int i=0;i<2;i++) for (int j=0;j<4;j++) for (int q=0;q<4;q++) acc[i][j][q]=0.f;

    for (int k0 = 0; k0 < CDIM; k0 += 64){
        #pragma unroll
        for (int ii = 0; ii < 4; ii++){
            int i = t + ii*256, row = i >> 3, q = i & 7;
            *(uint4*)&sA[row*PITCH + q*8] = *(const uint4*)&g_wvb[(c0 + row)*CDIM + k0 + q*8];
        }
        #pragma unroll
        for (int ii = 0; ii < 8; ii++){
            int i = t + ii*256, m = i >> 5, kp = i & 31;
            *(uint32_t*)&sB[m*PITCH + 2*kp] =
                pack2(g_KX[(b*MDIM + m)*CDIM + k0 + 2*kp], g_KX[(b*MDIM + m)*CDIM + k0 + 2*kp + 1]);
        }
        __syncthreads();
        #pragma unroll
        for (int ks = 0; ks < 4; ks++){
            int kb = ks*16;
            uint32_t a[2][4], bb[4][2];
            #pragma unroll
            for (int mi = 0; mi < 2; mi++){
                int r = wc + mi*16 + gr;
                a[mi][0] = *(uint32_t*)&sA[ r   *PITCH + kb + 2*tg];
                a[mi][1] = *(uint32_t*)&sA[(r+8)*PITCH + kb + 2*tg];
                a[mi][2] = *(uint32_t*)&sA[ r   *PITCH + kb + 2*tg + 8];
                a[mi][3] = *(uint32_t*)&sA[(r+8)*PITCH + kb + 2*tg + 8];
            }
            #pragma unroll
            for (int ni = 0; ni < 4; ni++){
                int rn = wm2 + ni*8 + gr;
                bb[ni][0] = *(uint32_t*)&sB[rn*PITCH + kb + 2*tg];
                bb[ni][1] = *(uint32_t*)&sB[rn*PITCH + kb + 2*tg + 8];
            }
            #pragma unroll
            for (int mi = 0; mi < 2; mi++)
                #pragma unroll
                for (int ni = 0; ni < 4; ni++)
                    mma16816(acc[mi][ni], a[mi][0], a[mi][1], a[mi][2], a[mi][3], bb[ni][0], bb[ni][1]);
        }
        __syncthreads();
    }
    #pragma unroll
    for (int mi = 0; mi < 2; mi++){
        int r0 = c0 + wc + mi*16 + gr;
        float g0 = g_gmax[b*CDIM + r0    ] + g_gsum[b*CDIM + r0    ]*(1.f/NDIM);
        float g1 = g_gmax[b*CDIM + r0 + 8] + g_gsum[b*CDIM + r0 + 8]*(1.f/NDIM);
        float b0 = bv[r0], b1 = bv[r0 + 8];
        #pragma unroll
        for (int ni = 0; ni < 4; ni++){
            int m0 = wm2 + ni*8 + 2*tg;
            float s0 = g_ksum[b*MDIM + m0], s1 = g_ksum[b*MDIM + m0 + 1];
            *(uint32_t*)&g_KVt[((size_t)(b*CDIM + r0    ))*MDIM + m0] =
                pack2(g0*(acc[mi][ni][0] + b0*s0), g0*(acc[mi][ni][1] + b0*s1));
            *(uint32_t*)&g_KVt[((size_t)(b*CDIM + r0 + 8))*MDIM + m0] =
                pack2(g1*(acc[mi][ni][2] + b1*s0), g1*(acc[mi][ni][3] + b1*s1));
        }
    }
}

// ---- K6: out[b][c][n] = x + gamma*norm[n]*sum_m KVt[c][m]*Qft[n][m] ----
__global__ __launch_bounds__(256) void k_out(const float* __restrict__ x,
                                             const float* __restrict__ gamma,
                                             float* __restrict__ out){
    __shared__ __nv_bfloat16 sA[128*PITCH];   // KVt [c][k=m]
    __shared__ __nv_bfloat16 sB[128*PITCH];   // Qft [n][k=m]
    __shared__ float snorm[128];
    const int t = threadIdx.x, b = blockIdx.z;
    const int c0 = blockIdx.x*128, n0 = blockIdx.y*128;
    const int lane = t & 31, w = t >> 5, gr = lane >> 2, tg = lane & 3;
    const int wc = (w & 3)*32, wn = (w >> 2)*64;
    float acc[2][8][4];
    #pragma unroll
    for (int i=0;i<2;i++) for (int j=0;j<8;j++) for (int q=0;q<4;q++) acc[i][j][q]=0.f;

    if (t < 128) snorm[t] = g_norm[b*NDIM + n0 + t];
    #pragma unroll
    for (int ii = 0; ii < 4; ii++){
        int i = t + ii*256, row = i >> 3, q = i & 7;
        *(uint4*)&sA[row*PITCH + q*8] = *(const uint4*)&g_KVt[((size_t)(b*CDIM + c0 + row))*MDIM + q*8];
        *(uint4*)&sB[row*PITCH + q*8] = *(const uint4*)&g_Qft[((size_t)(b*NDIM + n0 + row))*MDIM + q*8];
    }
    __syncthreads();
    #pragma unroll
    for (int ks = 0; ks < 4; ks++){
        int kb = ks*16;
        uint32_t a[2][4], bb[8][2];
        #pragma unroll
        for (int mi = 0; mi < 2; mi++){
            int r = wc + mi*16 + gr;
            a[mi][0] = *(uint32_t*)&sA[ r   *PITCH + kb + 2*tg];
            a[mi][1] = *(uint32_t*)&sA[(r+8)*PITCH + kb + 2*tg];
            a[mi][2] = *(uint32_t*)&sA[ r   *PITCH + kb + 2*tg + 8];
            a[mi][3] = *(uint32_t*)&sA[(r+8)*PITCH + kb + 2*tg + 8];
        }
        #pragma unroll
        for (int ni = 0; ni < 8; ni++){
            int rn = wn + ni*8 + gr;
            bb[ni][0] = *(uint32_t*)&sB[rn*PITCH + kb + 2*tg];
            bb[ni][1] = *(uint32_t*)&sB[rn*PITCH + kb + 2*tg + 8];
        }
        #pragma unroll
        for (int mi = 0; mi < 2; mi++)
            #pragma unroll
            for (int ni = 0; ni < 8; ni++)
                mma16816(acc[mi][ni], a[mi][0], a[mi][1], a[mi][2], a[mi][3], bb[ni][0], bb[ni][1]);
    }
    float gm = __ldg(gamma);
    #pragma unroll
    for (int mi = 0; mi < 2; mi++){
        int r = c0 + wc + mi*16 + gr;
        #pragma unroll
        for (int ni = 0; ni < 8; ni++){
            int col = wn + ni*8 + 2*tg;
            float nv0 = gm*snorm[col], nv1 = gm*snorm[col + 1];
            size_t i0 = ((size_t)(b*CDIM + r))*NDIM + n0 + col;
            size_t i1 = ((size_t)(b*CDIM + r + 8))*NDIM + n0 + col;
            float2 x0 = *(const float2*)&x[i0];
            float2 x1 = *(const float2*)&x[i1];
            float2 o0 = { x0.x + nv0*acc[mi][ni][0], x0.y + nv1*acc[mi][ni][1] };
            float2 o1 = { x1.x + nv0*acc[mi][ni][2], x1.y + nv1*acc[mi][ni][3] };
            *(float2*)&out[i0] = o0;
            *(float2*)&out[i1] = o1;
        }
    }
}

extern "C" void kernel_launch(void* const* d_in, const int* in_sizes, int n_in,
                              void* d_out, int out_size) {
    const float* x     = (const float*)d_in[0];
    const float* wq    = (const float*)d_in[1];
    const float* bq    = (const float*)d_in[2];
    const float* wk    = (const float*)d_in[3];
    const float* bk    = (const float*)d_in[4];
    const float* wv    = (const float*)d_in[5];
    const float* bv    = (const float*)d_in[6];
    const float* gamma = (const float*)d_in[7];
    float* out = (float*)d_out;

    k_prep<<<1024, 256>>>(wv);
    k_qk  <<<dim3(NDIM/128, BATCH), 256>>>(x, wq, bq, wk, bk);
    k_kx  <<<dim3(CDIM/128, NDIM/256, BATCH), 256>>>(x);
    k_norm<<<dim3(NDIM/256, BATCH), 256>>>();
    k_kv  <<<dim3(CDIM/128, BATCH), 256>>>(bv);
    k_out <<<dim3(CDIM/128, NDIM/128, BATCH), 256>>>(x, gamma, out);
}

// round 5
// speedup vs baseline: 1.1145x; 1.1145x over previous
#include <cuda_runtime.h>
#include <cuda_bf16.h>
#include <cstdint>

#define BATCH 8
#define CDIM  512
#define NDIM  4096
#define MDIM  64
#define EPSV  1e-6f
#define PITCH 72   // bf16 elems per smem row; 36 words -> stride 4 mod 32 banks: conflict-free frags

// ---- scratch (device globals; allocation is forbidden) ----
__device__ float         g_gate[BATCH*CDIM];
__device__ float         g_ksum[BATCH*MDIM];
__device__ float         g_KX[BATCH*MDIM*CDIM];
__device__ __nv_bfloat16 g_wvb[CDIM*CDIM];
__device__ __nv_bfloat16 g_Kf[BATCH*MDIM*NDIM];    // [b][m][n]
__device__ __nv_bfloat16 g_Qft[BATCH*NDIM*MDIM];   // [b][n][m]
__device__ __nv_bfloat16 g_KVt[BATCH*CDIM*MDIM];   // [b][c][m]

__device__ __forceinline__ uint32_t pack2(float a, float b){
    __nv_bfloat162 h = __floats2bfloat162_rn(a, b);
    return *reinterpret_cast<uint32_t*>(&h);
}
__device__ __forceinline__ float softplusf(float v){
    return v > 15.f ? v : log1pf(expf(v));
}
__device__ __forceinline__ void mma16816(float c[4], uint32_t a0, uint32_t a1, uint32_t a2, uint32_t a3,
                                         uint32_t b0, uint32_t b1){
    asm volatile("mma.sync.aligned.m16n8k16.row.col.f32.bf16.bf16.f32 "
                 "{%0,%1,%2,%3},{%4,%5,%6,%7},{%8,%9},{%0,%1,%2,%3};"
                 : "+f"(c[0]), "+f"(c[1]), "+f"(c[2]), "+f"(c[3])
                 : "r"(a0), "r"(a1), "r"(a2), "r"(a3), "r"(b0), "r"(b1));
}

// ---- K0: zero accumulators + convert wv -> bf16 (every replay) ----
__global__ __launch_bounds__(256) void k_prep(const float* __restrict__ wv){
    int i = blockIdx.x*256 + threadIdx.x;
    if (i < BATCH*MDIM*CDIM) g_KX[i] = 0.f;
    if (i < CDIM*CDIM)       g_wvb[i] = __float2bfloat16(wv[i]);
    if (i < BATCH*MDIM)      g_ksum[i] = 0.f;
}

// ---- K1: gate[b][c] = max_n x + mean_n x ----
__global__ __launch_bounds__(256) void k_gate(const float* __restrict__ x){
    int c = blockIdx.x, b = blockIdx.y;
    const float* p = x + ((size_t)(b*CDIM + c))*NDIM;
    float mx = -1e30f, sm = 0.f;
    for (int i = threadIdx.x; i < NDIM/4; i += 256){
        float4 v = ((const float4*)p)[i];
        mx = fmaxf(mx, fmaxf(fmaxf(v.x, v.y), fmaxf(v.z, v.w)));
        sm += (v.x + v.y) + (v.z + v.w);
    }
    for (int o = 16; o > 0; o >>= 1){
        mx = fmaxf(mx, __shfl_xor_sync(~0u, mx, o));
        sm += __shfl_xor_sync(~0u, sm, o);
    }
    __shared__ float smx[8], ssm[8];
    int w = threadIdx.x >> 5;
    if ((threadIdx.x & 31) == 0){ smx[w] = mx; ssm[w] = sm; }
    __syncthreads();
    if (threadIdx.x == 0){
        mx = smx[0]; sm = ssm[0];
        for (int i = 1; i < 8; i++){ mx = fmaxf(mx, smx[i]); sm += ssm[i]; }
        g_gate[b*CDIM + c] = mx + sm*(1.f/NDIM);
    }
}

// ---- K2: fused Q/K. One x pass: Kf[b][m][n] (+ksum), Qft[b][n][m] ----
__global__ __launch_bounds__(256) void k_qk(const float* __restrict__ x,
                                            const float* __restrict__ wq, const float* __restrict__ bq,
                                            const float* __restrict__ wk, const float* __restrict__ bk){
    __shared__ __nv_bfloat16 sWk[64*PITCH], sWq[64*PITCH], sX[128*PITCH];
    __shared__ float sSum[64];
    const int t = threadIdx.x, b = blockIdx.y, n0 = blockIdx.x*128;
    const int lane = t & 31, w = t >> 5, gr = lane >> 2, tg = lane & 3;
    const int wm = (w >> 2)*32, wn = (w & 3)*32;    // K output: rows m, cols n
    const int wr = (w & 3)*32, wc2 = (w >> 2)*32;   // Q output: rows n, cols m
    const float* xb = x + (size_t)b*CDIM*NDIM;
    float ak[2][4][4], aq[2][4][4];
    #pragma unroll
    for (int i=0;i<2;i++) for (int j=0;j<4;j++) for (int q=0;q<4;q++){ ak[i][j][q]=0.f; aq[i][j][q]=0.f; }
    if (t < 64) sSum[t] = 0.f;

    for (int k0 = 0; k0 < CDIM; k0 += 64){
        #pragma unroll
        for (int ii = 0; ii < 8; ii++){
            int i = t + ii*256, m = i >> 5, kp = i & 31;
            float2 v = *(const float2*)&wk[m*CDIM + k0 + 2*kp];
            *(uint32_t*)&sWk[m*PITCH + 2*kp] = pack2(v.x, v.y);
            float2 u = *(const float2*)&wq[m*CDIM + k0 + 2*kp];
            *(uint32_t*)&sWq[m*PITCH + 2*kp] = pack2(u.x, u.y);
        }
        #pragma unroll
        for (int ii = 0; ii < 16; ii++){
            int i = t + ii*256, kp = i >> 7, nn = i & 127;
            float v0 = xb[(size_t)(k0 + 2*kp    )*NDIM + n0 + nn];
            float v1 = xb[(size_t)(k0 + 2*kp + 1)*NDIM + n0 + nn];
            *(uint32_t*)&sX[nn*PITCH + 2*kp] = pack2(v0, v1);
        }
        __syncthreads();
        #pragma unroll
        for (int ks = 0; ks < 4; ks++){
            int kb = ks*16;
            {   // K = wk @ x
                uint32_t a[2][4], bb[4][2];
                #pragma unroll
                for (int mi = 0; mi < 2; mi++){
                    int r = wm + mi*16 + gr;
                    a[mi][0] = *(uint32_t*)&sWk[ r   *PITCH + kb + 2*tg];
                    a[mi][1] = *(uint32_t*)&sWk[(r+8)*PITCH + kb + 2*tg];
                    a[mi][2] = *(uint32_t*)&sWk[ r   *PITCH + kb + 2*tg + 8];
                    a[mi][3] = *(uint32_t*)&sWk[(r+8)*PITCH + kb + 2*tg + 8];
                }
                #pragma unroll
                for (int ni = 0; ni < 4; ni++){
                    int rn = wn + ni*8 + gr;
                    bb[ni][0] = *(uint32_t*)&sX[rn*PITCH + kb + 2*tg];
                    bb[ni][1] = *(uint32_t*)&sX[rn*PITCH + kb + 2*tg + 8];
                }
                #pragma unroll
                for (int mi = 0; mi < 2; mi++)
                    #pragma unroll
                    for (int ni = 0; ni < 4; ni++)
                        mma16816(ak[mi][ni], a[mi][0], a[mi][1], a[mi][2], a[mi][3], bb[ni][0], bb[ni][1]);
            }
            {   // Q^T = x^T @ wq^T
                uint32_t a[2][4], bb[4][2];
                #pragma unroll
                for (int mi = 0; mi < 2; mi++){
                    int r = wr + mi*16 + gr;
                    a[mi][0] = *(uint32_t*)&sX[ r   *PITCH + kb + 2*tg];
                    a[mi][1] = *(uint32_t*)&sX[(r+8)*PITCH + kb + 2*tg];
                    a[mi][2] = *(uint32_t*)&sX[ r   *PITCH + kb + 2*tg + 8];
                    a[mi][3] = *(uint32_t*)&sX[(r+8)*PITCH + kb + 2*tg + 8];
                }
                #pragma unroll
                for (int ni = 0; ni < 4; ni++){
                    int rn = wc2 + ni*8 + gr;
                    bb[ni][0] = *(uint32_t*)&sWq[rn*PITCH + kb + 2*tg];
                    bb[ni][1] = *(uint32_t*)&sWq[rn*PITCH + kb + 2*tg + 8];
                }
                #pragma unroll
                for (int mi = 0; mi < 2; mi++)
                    #pragma unroll
                    for (int ni = 0; ni < 4; ni++)
                        mma16816(aq[mi][ni], a[mi][0], a[mi][1], a[mi][2], a[mi][3], bb[ni][0], bb[ni][1]);
            }
        }
        __syncthreads();
    }
    // K epilogue: softplus, store Kf, row-sum partials
    #pragma unroll
    for (int mi = 0; mi < 2; mi++){
        int r0 = wm + mi*16 + gr;
        float bk0 = bk[r0], bk1 = bk[r0 + 8];
        float rs0 = 0.f, rs1 = 0.f;
        #pragma unroll
        for (int ni = 0; ni < 4; ni++){
            float v00 = softplusf(ak[mi][ni][0] + bk0);
            float v01 = softplusf(ak[mi][ni][1] + bk0);
            float v10 = softplusf(ak[mi][ni][2] + bk1);
            float v11 = softplusf(ak[mi][ni][3] + bk1);
            rs0 += v00 + v01; rs1 += v10 + v11;
            int col = n0 + wn + ni*8 + 2*tg;
            *(uint32_t*)&g_Kf[((size_t)(b*MDIM + r0    ))*NDIM + col] = pack2(v00, v01);
            *(uint32_t*)&g_Kf[((size_t)(b*MDIM + r0 + 8))*NDIM + col] = pack2(v10, v11);
        }
        atomicAdd(&sSum[r0], rs0);
        atomicAdd(&sSum[r0 + 8], rs1);
    }
    // Q epilogue: softplus, store transposed
    #pragma unroll
    for (int mi = 0; mi < 2; mi++){
        int r0 = wr + mi*16 + gr;
        #pragma unroll
        for (int ni = 0; ni < 4; ni++){
            int col = wc2 + ni*8 + 2*tg;
            float bq0 = bq[col], bq1 = bq[col + 1];
            float v00 = softplusf(aq[mi][ni][0] + bq0);
            float v01 = softplusf(aq[mi][ni][1] + bq1);
            float v10 = softplusf(aq[mi][ni][2] + bq0);
            float v11 = softplusf(aq[mi][ni][3] + bq1);
            *(uint32_t*)&g_Qft[((size_t)(b*NDIM + n0 + r0    ))*MDIM + col] = pack2(v00, v01);
            *(uint32_t*)&g_Qft[((size_t)(b*NDIM + n0 + r0 + 8))*MDIM + col] = pack2(v10, v11);
        }
    }
    __syncthreads();
    if (t < 64) atomicAdd(&g_ksum[b*MDIM + t], sSum[t]);
}

// ---- K3: KX[b][m][c] += sum_n Kf[m][n]*x[c][n]  (8-way n-split, atomics)
//      register-prefetch software pipeline hides DRAM latency behind MMAs ----
__global__ __launch_bounds__(256) void k_kx(const float* __restrict__ x){
    __shared__ __nv_bfloat16 sA[64*PITCH];    // Kf [m][k=n]
    __shared__ __nv_bfloat16 sB[128*PITCH];   // x  [c][k=n]
    const int t = threadIdx.x, b = blockIdx.z;
    const int c0 = blockIdx.x*128, ns0 = blockIdx.y*512;
    const int lane = t & 31, w = t >> 5, gr = lane >> 2, tg = lane & 3;
    const int wm = (w >> 2)*32, wc = (w & 3)*32;
    const float* xb = x + (size_t)b*CDIM*NDIM;
    float acc[2][4][4];
    #pragma unroll
    for (int i=0;i<2;i++) for (int j=0;j<4;j++) for (int q=0;q<4;q++) acc[i][j][q]=0.f;

    const int am = t >> 3, aq_ = t & 7;       // A tile thread mapping
    const int xw = t >> 5, xnp = t & 31;      // X tile thread mapping
    uint4  rA[2];
    float2 rX[16];

    // prologue: prefetch chunk 0
    #pragma unroll
    for (int ii = 0; ii < 2; ii++)
        rA[ii] = *(const uint4*)&g_Kf[((size_t)(b*MDIM + 32*ii + am))*NDIM + ns0 + aq_*8];
    #pragma unroll
    for (int ii = 0; ii < 16; ii++)
        rX[ii] = *(const float2*)&xb[(size_t)(c0 + 8*ii + xw)*NDIM + ns0 + 2*xnp];

    for (int kc = 0; kc < 512; kc += 64){
        // commit prefetched regs to smem
        #pragma unroll
        for (int ii = 0; ii < 2; ii++)
            *(uint4*)&sA[(32*ii + am)*PITCH + aq_*8] = rA[ii];
        #pragma unroll
        for (int ii = 0; ii < 16; ii++)
            *(uint32_t*)&sB[(8*ii + xw)*PITCH + 2*xnp] = pack2(rX[ii].x, rX[ii].y);
        __syncthreads();
        // issue next chunk's loads (overlap with MMA below)
        if (kc + 64 < 512){
            int nk1 = ns0 + kc + 64;
            #pragma unroll
            for (int ii = 0; ii < 2; ii++)
                rA[ii] = *(const uint4*)&g_Kf[((size_t)(b*MDIM + 32*ii + am))*NDIM + nk1 + aq_*8];
            #pragma unroll
            for (int ii = 0; ii < 16; ii++)
                rX[ii] = *(const float2*)&xb[(size_t)(c0 + 8*ii + xw)*NDIM + nk1 + 2*xnp];
        }
        #pragma unroll
        for (int ks = 0; ks < 4; ks++){
            int kb = ks*16;
            uint32_t a[2][4], bb[4][2];
            #pragma unroll
            for (int mi = 0; mi < 2; mi++){
                int r = wm + mi*16 + gr;
                a[mi][0] = *(uint32_t*)&sA[ r   *PITCH + kb + 2*tg];
                a[mi][1] = *(uint32_t*)&sA[(r+8)*PITCH + kb + 2*tg];
                a[mi][2] = *(uint32_t*)&sA[ r   *PITCH + kb + 2*tg + 8];
                a[mi][3] = *(uint32_t*)&sA[(r+8)*PITCH + kb + 2*tg + 8];
            }
            #pragma unroll
            for (int ni = 0; ni < 4; ni++){
                int rn = wc + ni*8 + gr;
                bb[ni][0] = *(uint32_t*)&sB[rn*PITCH + kb + 2*tg];
                bb[ni][1] = *(uint32_t*)&sB[rn*PITCH + kb + 2*tg + 8];
            }
            #pragma unroll
            for (int mi = 0; mi < 2; mi++)
                #pragma unroll
                for (int ni = 0; ni < 4; ni++)
                    mma16816(acc[mi][ni], a[mi][0], a[mi][1], a[mi][2], a[mi][3], bb[ni][0], bb[ni][1]);
        }
        __syncthreads();
    }
    #pragma unroll
    for (int mi = 0; mi < 2; mi++){
        int r = wm + mi*16 + gr;
        #pragma unroll
        for (int ni = 0; ni < 4; ni++){
            int col = c0 + wc + ni*8 + 2*tg;
            atomicAdd(&g_KX[(b*MDIM + r    )*CDIM + col    ], acc[mi][ni][0]);
            atomicAdd(&g_KX[(b*MDIM + r    )*CDIM + col + 1], acc[mi][ni][1]);
            atomicAdd(&g_KX[(b*MDIM + r + 8)*CDIM + col    ], acc[mi][ni][2]);
            atomicAdd(&g_KX[(b*MDIM + r + 8)*CDIM + col + 1], acc[mi][ni][3]);
        }
    }
}

// ---- K5: KVt[b][c][m] = gate[c]*(sum_c' wv[c][c']*KX[m][c'] + bv[c]*ksum[m]) ----
__global__ __launch_bounds__(256) void k_kv(const float* __restrict__ bv){
    __shared__ __nv_bfloat16 sA[128*PITCH];   // wv  [c][k]
    __shared__ __nv_bfloat16 sB[64*PITCH];    // KX  [m][k]
    const int t = threadIdx.x, b = blockIdx.y, c0 = blockIdx.x*128;
    const int lane = t & 31, w = t >> 5, gr = lane >> 2, tg = lane & 3;
    const int wc = (w & 3)*32, wm2 = (w >> 2)*32;
    float acc[2][4][4];
    #pragma unroll
    for (int i=0;i<2;i++) for (int j=0;j<4;j++) for (int q=0;q<4;q++) acc[i][j][q]=0.f;

    for (int k0 = 0; k0 < CDIM; k0 += 64){
        #pragma unroll
        for (int ii = 0; ii < 4; ii++){
            int i = t + ii*256, row = i >> 3, q = i & 7;
            *(uint4*)&sA[row*PITCH + q*8] = *(const uint4*)&g_wvb[(c0 + row)*CDIM + k0 + q*8];
        }
        #pragma unroll
        for (int ii = 0; ii < 8; ii++){
            int i = t + ii*256, m = i >> 5, kp = i & 31;
            *(uint32_t*)&sB[m*PITCH + 2*kp] =
                pack2(g_KX[(b*MDIM + m)*CDIM + k0 + 2*kp], g_KX[(b*MDIM + m)*CDIM + k0 + 2*kp + 1]);
        }
        __syncthreads();
        #pragma unroll
        for (int ks = 0; ks < 4; ks++){
            int kb = ks*16;
            uint32_t a[2][4], bb[4][2];
            #pragma unroll
            for (int mi = 0; mi < 2; mi++){
                int r = wc + mi*16 + gr;
                a[mi][0] = *(uint32_t*)&sA[ r   *PITCH + kb + 2*tg];
                a[mi][1] = *(uint32_t*)&sA[(r+8)*PITCH + kb + 2*tg];
                a[mi][2] = *(uint32_t*)&sA[ r   *PITCH + kb + 2*tg + 8];
                a[mi][3] = *(uint32_t*)&sA[(r+8)*PITCH + kb + 2*tg + 8];
            }
            #pragma unroll
            for (int ni = 0; ni < 4; ni++){
                int rn = wm2 + ni*8 + gr;
                bb[ni][0] = *(uint32_t*)&sB[rn*PITCH + kb + 2*tg];
                bb[ni][1] = *(uint32_t*)&sB[rn*PITCH + kb + 2*tg + 8];
            }
            #pragma unroll
            for (int mi = 0; mi < 2; mi++)
                #pragma unroll
                for (int ni = 0; ni < 4; ni++)
                    mma16816(acc[mi][ni], a[mi][0], a[mi][1], a[mi][2], a[mi][3], bb[ni][0], bb[ni][1]);
        }
        __syncthreads();
    }
    #pragma unroll
    for (int mi = 0; mi < 2; mi++){
        int r0 = c0 + wc + mi*16 + gr;
        float g0 = g_gate[b*CDIM + r0], g1 = g_gate[b*CDIM + r0 + 8];
        float b0 = bv[r0], b1 = bv[r0 + 8];
        #pragma unroll
        for (int ni = 0; ni < 4; ni++){
            int m0 = wm2 + ni*8 + 2*tg;
            float s0 = g_ksum[b*MDIM + m0], s1 = g_ksum[b*MDIM + m0 + 1];
            *(uint32_t*)&g_KVt[((size_t)(b*CDIM + r0    ))*MDIM + m0] =
                pack2(g0*(acc[mi][ni][0] + b0*s0), g0*(acc[mi][ni][1] + b0*s1));
            *(uint32_t*)&g_KVt[((size_t)(b*CDIM + r0 + 8))*MDIM + m0] =
                pack2(g1*(acc[mi][ni][2] + b1*s0), g1*(acc[mi][ni][3] + b1*s1));
        }
    }
}

// ---- K6: out = x + gamma*norm[n]*(KVt @ Qft^T); norm computed in-kernel ----
__global__ __launch_bounds__(256) void k_out(const float* __restrict__ x,
                                             const float* __restrict__ gamma,
                                             float* __restrict__ out){
    __shared__ __nv_bfloat16 sA[128*PITCH];   // KVt [c][k=m]
    __shared__ __nv_bfloat16 sB[128*PITCH];   // Qft [n][k=m]
    __shared__ float snorm[128], sk[64];
    const int t = threadIdx.x, b = blockIdx.z;
    const int c0 = blockIdx.x*128, n0 = blockIdx.y*128;
    const int lane = t & 31, w = t >> 5, gr = lane >> 2, tg = lane & 3;
    const int wc = (w & 3)*32, wn = (w >> 2)*64;
    float acc[2][8][4];
    #pragma unroll
    for (int i=0;i<2;i++) for (int j=0;j<8;j++) for (int q=0;q<4;q++) acc[i][j][q]=0.f;

    if (t < 64) sk[t] = g_ksum[b*MDIM + t] + EPSV;
    #pragma unroll
    for (int ii = 0; ii < 4; ii++){
        int i = t + ii*256, row = i >> 3, q = i & 7;
        *(uint4*)&sA[row*PITCH + q*8] = *(const uint4*)&g_KVt[((size_t)(b*CDIM + c0 + row))*MDIM + q*8];
        *(uint4*)&sB[row*PITCH + q*8] = *(const uint4*)&g_Qft[((size_t)(b*NDIM + n0 + row))*MDIM + q*8];
    }
    __syncthreads();
    // fused norm: denom[n] = sum_m Qft[n][m]*(ksum[m]+eps)
    if (t < 128){
        const __nv_bfloat162* row = (const __nv_bfloat162*)&sB[t*PITCH];
        float d = 0.f;
        #pragma unroll
        for (int j = 0; j < 32; j++){
            float2 v = __bfloat1622float2(row[j]);
            d += v.x*sk[2*j] + v.y*sk[2*j + 1];
        }
        snorm[t] = 1.f/d;
    }
    #pragma unroll
    for (int ks = 0; ks < 4; ks++){
        int kb = ks*16;
        uint32_t a[2][4], bb[8][2];
        #pragma unroll
        for (int mi = 0; mi < 2; mi++){
            int r = wc + mi*16 + gr;
            a[mi][0] = *(uint32_t*)&sA[ r   *PITCH + kb + 2*tg];
            a[mi][1] = *(uint32_t*)&sA[(r+8)*PITCH + kb + 2*tg];
            a[mi][2] = *(uint32_t*)&sA[ r   *PITCH + kb + 2*tg + 8];
            a[mi][3] = *(uint32_t*)&sA[(r+8)*PITCH + kb + 2*tg + 8];
        }
        #pragma unroll
        for (int ni = 0; ni < 8; ni++){
            int rn = wn + ni*8 + gr;
            bb[ni][0] = *(uint32_t*)&sB[rn*PITCH + kb + 2*tg];
            bb[ni][1] = *(uint32_t*)&sB[rn*PITCH + kb + 2*tg + 8];
        }
        #pragma unroll
        for (int mi = 0; mi < 2; mi++)
            #pragma unroll
            for (int ni = 0; ni < 8; ni++)
                mma16816(acc[mi][ni], a[mi][0], a[mi][1], a[mi][2], a[mi][3], bb[ni][0], bb[ni][1]);
    }
    __syncthreads();   // snorm visible to all warps
    float gm = __ldg(gamma);
    #pragma unroll
    for (int mi = 0; mi < 2; mi++){
        int r = c0 + wc + mi*16 + gr;
        #pragma unroll
        for (int ni = 0; ni < 8; ni++){
            int col = wn + ni*8 + 2*tg;
            float nv0 = gm*snorm[col], nv1 = gm*snorm[col + 1];
            size_t i0 = ((size_t)(b*CDIM + r))*NDIM + n0 + col;
            size_t i1 = ((size_t)(b*CDIM + r + 8))*NDIM + n0 + col;
            float2 x0 = *(const float2*)&x[i0];
            float2 x1 = *(const float2*)&x[i1];
            float2 o0 = { x0.x + nv0*acc[mi][ni][0], x0.y + nv1*acc[mi][ni][1] };
            float2 o1 = { x1.x + nv0*acc[mi][ni][2], x1.y + nv1*acc[mi][ni][3] };
            *(float2*)&out[i0] = o0;
            *(float2*)&out[i1] = o1;
        }
    }
}

extern "C" void kernel_launch(void* const* d_in, const int* in_sizes, int n_in,
                              void* d_out, int out_size) {
    const float* x     = (const float*)d_in[0];
    const float* wq    = (const float*)d_in[1];
    const float* bq    = (const float*)d_in[2];
    const float* wk    = (const float*)d_in[3];
    const float* bk    = (const float*)d_in[4];
    const float* wv    = (const float*)d_in[5];
    const float* bv    = (const float*)d_in[6];
    const float* gamma = (const float*)d_in[7];
    float* out = (float*)d_out;

    k_prep<<<1024, 256>>>(wv);
    k_gate<<<dim3(CDIM, BATCH), 256>>>(x);
    k_qk  <<<dim3(NDIM/128, BATCH), 256>>>(x, wq, bq, wk, bk);
    k_kx  <<<dim3(CDIM/128, NDIM/512, BATCH), 256>>>(x);
    k_kv  <<<dim3(CDIM/128, BATCH), 256>>>(bv);
    k_out <<<dim3(CDIM/128, NDIM/128, BATCH), 256>>>(x, gamma, out);
}